// round 6
// baseline (speedup 1.0000x reference)
#include <cuda_runtime.h>
#include <math.h>

// ---------------------------------------------------------------------------
// Yolact head: FPN + shared prediction head, fp32.
// Output buffer layout (harness flattens the (out, prior) tuple):
//   [0, 8*17742*117)            : out  (B, rows, 117) fp32
//   [8*17742*117, +17742*4)     : prior (17742, 4)    fp32
// Level row offsets: p3(67x67)=0, p4(33x33)=13467, p5(16x16)=16734,
//                    p6(8x8)=17502, p7(4x4)=17694; total 17742 rows.
// ---------------------------------------------------------------------------

#define BATCH 8
#define TOTAL_ROWS 17742
#define OUT_ELEMS (8u * 17742u * 117u)   // 16,606,512

// scratch (device globals; no allocation allowed)
__device__ float g_x5[8 * 256 * 18 * 18];
__device__ float g_p5[8 * 256 * 16 * 16];
__device__ float g_x4[8 * 256 * 35 * 35];
__device__ float g_p4[8 * 256 * 33 * 33];
__device__ float g_x3[8 * 256 * 69 * 69];
__device__ float g_p3[8 * 256 * 67 * 67];
__device__ float g_p6[8 * 256 * 8 * 8];
__device__ float g_p7[8 * 256 * 4 * 4];
__device__ float g_u [8 * 256 * 67 * 67];
__device__ float g_wh[351 * 2304];
__device__ float g_bh[351];

// ---------------------------------------------------------------------------
// Implicit-GEMM conv. KW: 1 or 3. PAD: 0/1. EPI: 0=none, 1=relu, 2=heads.
// Block tile: 128 (Cout) x 128 (pixels), BK=8, 256 threads, 8x8 micro-tile
// with SPLIT fragments (conflict-free LDS.128), DOUBLE-BUFFERED smem tiles:
// global loads for tile k+1 are issued before the FMA loop on tile k, so the
// ~577-cycle load latency is hidden under ~2000 issue-cycles of FMAs.
// One __syncthreads() per k-iteration.
// K is always a multiple of 8 here (2048/1024/512 for 1x1, 2304 for 3x3).
// ---------------------------------------------------------------------------
template <int KW, int PAD, int EPI>
__global__ __launch_bounds__(256)
void conv_gemm(const float* __restrict__ in, const float* __restrict__ w,
               const float* __restrict__ bias, float* __restrict__ out,
               int Cin, int Cout, int IH, int IW, int OH, int OW,
               int rowOff)
{
    const int K = Cin * KW * KW;
    const int N = OH * OW;
    const int b  = blockIdx.z;
    const int om = blockIdx.y * 128;
    const int nn = blockIdx.x * 128;
    const int tid = threadIdx.x;
    const int tx = tid & 15;      // pixel dim
    const int ty = tid >> 4;      // cout  dim

    __shared__ float As[2][8][128];
    __shared__ float Bs[2][8][128];

    float acc[8][8];
    #pragma unroll
    for (int i = 0; i < 8; i++)
        #pragma unroll
        for (int j = 0; j < 8; j++) acc[i][j] = 0.f;

    const float* __restrict__ inb = in + (size_t)b * Cin * IH * IW;

    // B-load coords (fixed per thread): n index within tile
    const int n_idx = tid & 127;
    const int ng = nn + n_idx;
    const bool nok = ng < N;
    const int oy = nok ? ng / OW : 0;
    const int ox = nok ? ng % OW : 0;
    const int kb = tid >> 7;      // 0 or 1

    // A-load coords: each thread loads one float4 of weights along k
    const int a_o  = tid >> 1;        // 0..127
    const int a_kq = (tid & 1) * 4;   // 0 or 4
    const int ao_g = om + a_o;
    const bool aok = ao_g < Cout;

    float4 va;          // staged A fragment (global -> reg)
    float  vb[4];       // staged B fragments

    auto load_tile = [&](int k0) {
        va = make_float4(0.f, 0.f, 0.f, 0.f);
        if (aok)
            va = *reinterpret_cast<const float4*>(w + (size_t)ao_g * K + (k0 + a_kq));
        #pragma unroll
        for (int pass = 0; pass < 4; pass++) {
            int kg = k0 + kb + pass * 2;
            float v = 0.f;
            if (nok) {
                int ci, iy, ix;
                if (KW == 1) { ci = kg; iy = oy; ix = ox; }
                else {
                    ci = kg / 9;
                    int r = kg - ci * 9;
                    int ky = r / 3, kx = r - ky * 3;
                    iy = oy + ky - PAD;
                    ix = ox + kx - PAD;
                }
                if (iy >= 0 && iy < IH && ix >= 0 && ix < IW)
                    v = inb[(size_t)ci * IH * IW + iy * IW + ix];
            }
            vb[pass] = v;
        }
    };

    auto store_tile = [&](int buf) {
        As[buf][a_kq + 0][a_o] = va.x;
        As[buf][a_kq + 1][a_o] = va.y;
        As[buf][a_kq + 2][a_o] = va.z;
        As[buf][a_kq + 3][a_o] = va.w;
        #pragma unroll
        for (int pass = 0; pass < 4; pass++)
            Bs[buf][kb + pass * 2][n_idx] = vb[pass];
    };

    auto compute = [&](int buf) {
        #pragma unroll
        for (int kk = 0; kk < 8; kk++) {
            float4 a0 = *reinterpret_cast<const float4*>(&As[buf][kk][ty * 4]);
            float4 a1 = *reinterpret_cast<const float4*>(&As[buf][kk][64 + ty * 4]);
            float4 b0 = *reinterpret_cast<const float4*>(&Bs[buf][kk][tx * 4]);
            float4 b1 = *reinterpret_cast<const float4*>(&Bs[buf][kk][64 + tx * 4]);
            float av[8] = {a0.x, a0.y, a0.z, a0.w, a1.x, a1.y, a1.z, a1.w};
            float bv[8] = {b0.x, b0.y, b0.z, b0.w, b1.x, b1.y, b1.z, b1.w};
            #pragma unroll
            for (int i = 0; i < 8; i++)
                #pragma unroll
                for (int j = 0; j < 8; j++)
                    acc[i][j] = fmaf(av[i], bv[j], acc[i][j]);
        }
    };

    // prologue: fill buffer 0
    load_tile(0);
    store_tile(0);
    __syncthreads();

    int cur = 0;
    for (int k0 = 8; k0 < K; k0 += 8) {
        load_tile(k0);          // LDGs in flight during compute below
        compute(cur);
        store_tile(1 - cur);    // safe: no thread reads 1-cur this iteration
        __syncthreads();
        cur ^= 1;
    }
    compute(cur);               // last tile

    // ---- epilogue (split-fragment index mapping) ----
    #pragma unroll
    for (int i = 0; i < 8; i++) {
        int o = om + ((i < 4) ? (ty * 4 + i) : (64 + ty * 4 + i - 4));
        if (o >= Cout) continue;
        float bval = bias[o];
        #pragma unroll
        for (int j = 0; j < 8; j++) {
            int n = nn + ((j < 4) ? (tx * 4 + j) : (64 + tx * 4 + j - 4));
            if (n >= N) continue;
            float v = acc[i][j] + bval;
            if (EPI == 1) v = fmaxf(v, 0.f);
            if (EPI <= 1) {
                out[((size_t)b * Cout + o) * N + n] = v;
            } else {
                int p, c;
                if (o < 12)       { p = o >> 2;       c = o & 3; }
                else if (o < 255) { int q = o - 12;   p = q / 81; c = 4 + (q - p * 81); }
                else              { int q = o - 255;  p = q >> 5; c = 85 + (q & 31); v = tanhf(v); }
                size_t row = (size_t)rowOff + (size_t)n * 3 + p;
                out[((size_t)b * TOTAL_ROWS + row) * 117 + c] = v;
            }
        }
    }
}

// bilinear resize (half-pixel centers, edge clamp) + accumulate into dst
__global__ void resize_add(const float* __restrict__ src, float* __restrict__ dst,
                           int IH, int IW, int OH, int OW)
{
    int idx = blockIdx.x * blockDim.x + threadIdx.x;
    int total = BATCH * 256 * OH * OW;
    if (idx >= total) return;
    int ox = idx % OW;
    int t  = idx / OW;
    int oyv = t % OH;
    int bc = t / OH;
    float sy = (oyv + 0.5f) * (float)IH / (float)OH - 0.5f;
    float sx = (ox  + 0.5f) * (float)IW / (float)OW - 0.5f;
    int y0 = (int)floorf(sy); float fy = sy - y0;
    int x0 = (int)floorf(sx); float fx = sx - x0;
    int y0c = min(max(y0, 0), IH - 1), y1c = min(max(y0 + 1, 0), IH - 1);
    int x0c = min(max(x0, 0), IW - 1), x1c = min(max(x0 + 1, 0), IW - 1);
    const float* s = src + (size_t)bc * IH * IW;
    float v = (1.f - fy) * ((1.f - fx) * s[y0c * IW + x0c] + fx * s[y0c * IW + x1c])
            +         fy * ((1.f - fx) * s[y1c * IW + x0c] + fx * s[y1c * IW + x1c]);
    dst[idx] += v;
}

__global__ void downsample2(const float* __restrict__ src, float* __restrict__ dst,
                            int IH, int IW, int OH, int OW)
{
    int idx = blockIdx.x * blockDim.x + threadIdx.x;
    int total = BATCH * 256 * OH * OW;
    if (idx >= total) return;
    int ox = idx % OW;
    int t  = idx / OW;
    int oyv = t % OH;
    int bc = t / OH;
    dst[idx] = src[((size_t)bc * IH + 2 * oyv) * IW + 2 * ox];
}

__global__ void concat_heads(const float* __restrict__ bw, const float* __restrict__ bb,
                             const float* __restrict__ cw, const float* __restrict__ cb,
                             const float* __restrict__ mw, const float* __restrict__ mb)
{
    int idx = blockIdx.x * blockDim.x + threadIdx.x;
    if (idx < 351 * 2304) {
        int o = idx / 2304, k = idx - o * 2304;
        float v;
        if (o < 12)       v = bw[idx];
        else if (o < 255) v = cw[(o - 12) * 2304 + k];
        else              v = mw[(o - 255) * 2304 + k];
        g_wh[idx] = v;
    }
    if (idx < 351) {
        g_bh[idx] = (idx < 12) ? bb[idx] : (idx < 255) ? cb[idx - 12] : mb[idx - 255];
    }
}

__global__ void priors_kernel(float* __restrict__ out)
{
    int idx = blockIdx.x * blockDim.x + threadIdx.x;
    if (idx >= TOTAL_ROWS) return;
    int ch, cw, base;
    if (idx < 13467)      { ch = 67; cw = 67; base = 0; }
    else if (idx < 16734) { ch = 33; cw = 33; base = 13467; }
    else if (idx < 17502) { ch = 16; cw = 16; base = 16734; }
    else if (idx < 17694) { ch = 8;  cw = 8;  base = 17502; }
    else                  { ch = 4;  cw = 4;  base = 17694; }
    int q = idx - base;
    int p = q % 3;
    int n = q / 3;
    int y = n / cw, x = n - y * cw;
    const float ar[3] = {1.0f, 0.5f, 2.0f};
    out[idx * 4 + 0] = (x + 0.5f) / cw;
    out[idx * 4 + 1] = (y + 0.5f) / ch;
    out[idx * 4 + 2] = 3.0f * ar[p] / cw;
    out[idx * 4 + 3] = 3.0f / ar[p] / ch;
}

static inline int cdiv(int a, int b) { return (a + b - 1) / b; }

extern "C" void kernel_launch(void* const* d_in, const int* in_sizes, int n_in,
                              void* d_out, int out_size)
{
    const float* c3      = (const float*)d_in[0];
    const float* c4      = (const float*)d_in[1];
    const float* c5      = (const float*)d_in[2];
    const float* lat_w5  = (const float*)d_in[3];
    const float* lat_b5  = (const float*)d_in[4];
    const float* lat_w4  = (const float*)d_in[5];
    const float* lat_b4  = (const float*)d_in[6];
    const float* lat_w3  = (const float*)d_in[7];
    const float* lat_b3  = (const float*)d_in[8];
    const float* pred_w0 = (const float*)d_in[9];
    const float* pred_b0 = (const float*)d_in[10];
    const float* pred_w1 = (const float*)d_in[11];
    const float* pred_b1 = (const float*)d_in[12];
    const float* pred_w2 = (const float*)d_in[13];
    const float* pred_b2 = (const float*)d_in[14];
    const float* up_w    = (const float*)d_in[15];
    const float* up_b    = (const float*)d_in[16];
    const float* bbox_w  = (const float*)d_in[17];
    const float* bbox_b  = (const float*)d_in[18];
    const float* conf_w  = (const float*)d_in[19];
    const float* conf_b  = (const float*)d_in[20];
    const float* mask_w  = (const float*)d_in[21];
    const float* mask_b  = (const float*)d_in[22];

    float* out = (float*)d_out;

    float *x5, *p5, *x4, *p4, *x3, *p3, *p6, *p7, *u, *wh, *bh;
    cudaGetSymbolAddress((void**)&x5, g_x5);
    cudaGetSymbolAddress((void**)&p5, g_p5);
    cudaGetSymbolAddress((void**)&x4, g_x4);
    cudaGetSymbolAddress((void**)&p4, g_p4);
    cudaGetSymbolAddress((void**)&x3, g_x3);
    cudaGetSymbolAddress((void**)&p3, g_p3);
    cudaGetSymbolAddress((void**)&p6, g_p6);
    cudaGetSymbolAddress((void**)&p7, g_p7);
    cudaGetSymbolAddress((void**)&u,  g_u);
    cudaGetSymbolAddress((void**)&wh, g_wh);
    cudaGetSymbolAddress((void**)&bh, g_bh);

    // weight concat + priors (independent of the conv chain)
    concat_heads<<<cdiv(351 * 2304, 256), 256>>>(bbox_w, bbox_b, conf_w, conf_b, mask_w, mask_b);
    priors_kernel<<<cdiv(TOTAL_ROWS, 256), 256>>>(out + OUT_ELEMS);

    // FPN (Cout=256 -> 2 tiles of 128)
    conv_gemm<1, 0, 0><<<dim3(cdiv(18 * 18, 128), 2, 8), 256>>>(c5, lat_w5, lat_b5, x5, 2048, 256, 18, 18, 18, 18, 0);
    conv_gemm<3, 0, 1><<<dim3(cdiv(16 * 16, 128), 2, 8), 256>>>(x5, pred_w0, pred_b0, p5, 256, 256, 18, 18, 16, 16, 0);

    conv_gemm<1, 0, 0><<<dim3(cdiv(35 * 35, 128), 2, 8), 256>>>(c4, lat_w4, lat_b4, x4, 1024, 256, 35, 35, 35, 35, 0);
    resize_add<<<cdiv(BATCH * 256 * 35 * 35, 256), 256>>>(x5, x4, 18, 18, 35, 35);
    conv_gemm<3, 0, 1><<<dim3(cdiv(33 * 33, 128), 2, 8), 256>>>(x4, pred_w1, pred_b1, p4, 256, 256, 35, 35, 33, 33, 0);

    conv_gemm<1, 0, 0><<<dim3(cdiv(69 * 69, 128), 2, 8), 256>>>(c3, lat_w3, lat_b3, x3, 512, 256, 69, 69, 69, 69, 0);
    resize_add<<<cdiv(BATCH * 256 * 69 * 69, 256), 256>>>(x4, x3, 35, 35, 69, 69);
    conv_gemm<3, 0, 1><<<dim3(cdiv(67 * 67, 128), 2, 8), 256>>>(x3, pred_w2, pred_b2, p3, 256, 256, 69, 69, 67, 67, 0);

    downsample2<<<cdiv(BATCH * 256 * 8 * 8, 256), 256>>>(p5, p6, 16, 16, 8, 8);
    downsample2<<<cdiv(BATCH * 256 * 4 * 4, 256), 256>>>(p6, p7, 8, 8, 4, 4);

    // shared head per level (head Cout=351 -> 3 tiles of 128)
    struct { const float* p; int H; int rowOff; } LV[5] = {
        {p3, 67, 0}, {p4, 33, 13467}, {p5, 16, 16734}, {p6, 8, 17502}, {p7, 4, 17694}
    };
    for (int l = 0; l < 5; l++) {
        int H = LV[l].H;
        int nb = cdiv(H * H, 128);
        conv_gemm<3, 1, 1><<<dim3(nb, 2, 8), 256>>>(LV[l].p, up_w, up_b, u, 256, 256, H, H, H, H, 0);
        conv_gemm<3, 1, 2><<<dim3(nb, 3, 8), 256>>>(u, wh, bh, out, 256, 351, H, H, H, H, LV[l].rowOff);
    }
}

// round 7
// speedup vs baseline: 1.2428x; 1.2428x over previous
#include <cuda_runtime.h>
#include <math.h>

// ---------------------------------------------------------------------------
// Yolact head: FPN + shared prediction head, fp32, level-merged launches.
// Output: [0, 8*17742*117) out (B,rows,117); then prior (17742,4).
// Levels (concat pixel space, per batch): p3 4489 | p4 1089 | p5 256 | p6 64 | p7 16
// pixBase {0,4489,5578,5834,5898}, total 5914. rowOff = pixBase*3.
// ---------------------------------------------------------------------------

#define BATCH 8
#define TOTAL_ROWS 17742
#define OUT_ELEMS (8u * 17742u * 117u)
#define CPIX 5914            // concat pixels per (b, channel)

__device__ float g_x5[8 * 256 * 18 * 18];
__device__ float g_x4[8 * 256 * 35 * 35];
__device__ float g_x3[8 * 256 * 69 * 69];
__device__ float g_p [8 * 256 * CPIX];   // p3..p7 concat
__device__ float g_u [8 * 256 * CPIX];   // up-conv output concat
__device__ float g_wh[351 * 2304];
__device__ float g_bh[351];

// ---------------------------------------------------------------------------
// Shared double-buffered GEMM mainloop: 128x128 tile, BK=8, 8x8 split micro-tile.
// ---------------------------------------------------------------------------
template <int KW, int PAD>
__device__ __forceinline__ void gemm_loop(
    const float* __restrict__ w, int K, int Cout, int om,
    const float* __restrict__ inb, int IH, int IW, int OW,
    bool nok, int oy, int ox, int tid,
    float (&acc)[8][8], float (&As)[2][8][128], float (&Bs)[2][8][128])
{
    const int n_idx = tid & 127;
    const int kb = tid >> 7;
    const int a_o = tid >> 1;
    const int a_kq = (tid & 1) * 4;
    const int ao_g = om + a_o;
    const bool aok = ao_g < Cout;
    const int tx = tid & 15, ty = tid >> 4;

    float4 va; float vb[4];

    auto load_tile = [&](int k0) {
        va = make_float4(0.f, 0.f, 0.f, 0.f);
        if (aok)
            va = *reinterpret_cast<const float4*>(w + (size_t)ao_g * K + (k0 + a_kq));
        #pragma unroll
        for (int pass = 0; pass < 4; pass++) {
            int kg = k0 + kb + pass * 2;
            float v = 0.f;
            if (nok) {
                int ci, iy, ix;
                if (KW == 1) { ci = kg; iy = oy; ix = ox; }
                else {
                    ci = kg / 9;
                    int r = kg - ci * 9;
                    int ky = r / 3, kx = r - ky * 3;
                    iy = oy + ky - PAD;
                    ix = ox + kx - PAD;
                }
                if (iy >= 0 && iy < IH && ix >= 0 && ix < IW)
                    v = inb[(size_t)ci * IH * IW + iy * IW + ix];
            }
            vb[pass] = v;
        }
    };
    auto store_tile = [&](int buf) {
        As[buf][a_kq + 0][a_o] = va.x;
        As[buf][a_kq + 1][a_o] = va.y;
        As[buf][a_kq + 2][a_o] = va.z;
        As[buf][a_kq + 3][a_o] = va.w;
        #pragma unroll
        for (int pass = 0; pass < 4; pass++)
            Bs[buf][kb + pass * 2][n_idx] = vb[pass];
    };
    auto compute = [&](int buf) {
        #pragma unroll
        for (int kk = 0; kk < 8; kk++) {
            float4 a0 = *reinterpret_cast<const float4*>(&As[buf][kk][ty * 4]);
            float4 a1 = *reinterpret_cast<const float4*>(&As[buf][kk][64 + ty * 4]);
            float4 b0 = *reinterpret_cast<const float4*>(&Bs[buf][kk][tx * 4]);
            float4 b1 = *reinterpret_cast<const float4*>(&Bs[buf][kk][64 + tx * 4]);
            float av[8] = {a0.x, a0.y, a0.z, a0.w, a1.x, a1.y, a1.z, a1.w};
            float bv[8] = {b0.x, b0.y, b0.z, b0.w, b1.x, b1.y, b1.z, b1.w};
            #pragma unroll
            for (int i = 0; i < 8; i++)
                #pragma unroll
                for (int j = 0; j < 8; j++)
                    acc[i][j] = fmaf(av[i], bv[j], acc[i][j]);
        }
    };

    load_tile(0);
    store_tile(0);
    __syncthreads();
    int cur = 0;
    for (int k0 = 8; k0 < K; k0 += 8) {
        load_tile(k0);
        compute(cur);
        store_tile(1 - cur);
        __syncthreads();
        cur ^= 1;
    }
    compute(cur);
}

// ---------------------------------------------------------------------------
// Plain conv (lat 1x1 convs): NCHW in -> NCHW out, no activation.
// ---------------------------------------------------------------------------
__global__ __launch_bounds__(256)
void conv_lat(const float* __restrict__ in, const float* __restrict__ w,
              const float* __restrict__ bias, float* __restrict__ out,
              int Cin, int HW)
{
    const int b  = blockIdx.z;
    const int om = blockIdx.y * 128;
    const int nn = blockIdx.x * 128;
    const int tid = threadIdx.x;

    __shared__ float As[2][8][128];
    __shared__ float Bs[2][8][128];
    float acc[8][8];
    #pragma unroll
    for (int i = 0; i < 8; i++)
        #pragma unroll
        for (int j = 0; j < 8; j++) acc[i][j] = 0.f;

    const float* inb = in + (size_t)b * Cin * HW;
    const int n_idx = tid & 127;
    const int ng = nn + n_idx;
    const bool nok = ng < HW;
    gemm_loop<1, 0>(w, Cin, 256, om, inb, 1, HW, HW, nok, 0, nok ? ng : 0, tid, acc, As, Bs);

    const int tx = tid & 15, ty = tid >> 4;
    #pragma unroll
    for (int i = 0; i < 8; i++) {
        int o = om + ((i < 4) ? (ty * 4 + i) : (64 + ty * 4 + i - 4));
        float bval = bias[o];
        #pragma unroll
        for (int j = 0; j < 8; j++) {
            int n = nn + ((j < 4) ? (tx * 4 + j) : (64 + tx * 4 + j - 4));
            if (n >= HW) continue;
            out[((size_t)b * 256 + o) * HW + n] = acc[i][j] + bval;
        }
    }
}

// ---------------------------------------------------------------------------
// Merged pred convs (3 levels): 3x3 pad0, relu, write into g_p concat.
// level0(67,in 69)=pred_w2, level1(33,in 35)=pred_w1, level2(16,in 18)=pred_w0
// grid.x = 36+9+2 = 47
// ---------------------------------------------------------------------------
__global__ __launch_bounds__(256)
void conv_pred_merged(const float* __restrict__ x3, const float* __restrict__ x4,
                      const float* __restrict__ x5,
                      const float* __restrict__ w0, const float* __restrict__ w1,
                      const float* __restrict__ w2,
                      const float* __restrict__ b0, const float* __restrict__ b1,
                      const float* __restrict__ b2,
                      float* __restrict__ dst)
{
    int tl = blockIdx.x, l;
    if (tl < 36)      { l = 0; }
    else if (tl < 45) { l = 1; tl -= 36; }
    else              { l = 2; tl -= 45; }
    const int OWs[3] = {67, 33, 16};
    const int IHs[3] = {69, 35, 18};
    const int PB[3]  = {0, 4489, 5578};
    const float* ins[3] = {x3, x4, x5};
    const float* ws[3]  = {w2, w1, w0};   // level->weight mapping
    const float* bs[3]  = {b2, b1, b0};

    const int OW = OWs[l], IH = IHs[l], N = OW * OW;
    const int b  = blockIdx.z;
    const int om = blockIdx.y * 128;
    const int nn = tl * 128;
    const int tid = threadIdx.x;

    __shared__ float As[2][8][128];
    __shared__ float Bs[2][8][128];
    float acc[8][8];
    #pragma unroll
    for (int i = 0; i < 8; i++)
        #pragma unroll
        for (int j = 0; j < 8; j++) acc[i][j] = 0.f;

    const float* inb = ins[l] + (size_t)b * 256 * IH * IH;
    const int n_idx = tid & 127;
    const int ng = nn + n_idx;
    const bool nok = ng < N;
    const int oy = nok ? ng / OW : 0;
    const int ox = nok ? ng % OW : 0;

    gemm_loop<3, 0>(ws[l], 2304, 256, om, inb, IH, IH, OW, nok, oy, ox, tid, acc, As, Bs);

    const float* bias = bs[l];
    const int tx = tid & 15, ty = tid >> 4;
    #pragma unroll
    for (int i = 0; i < 8; i++) {
        int o = om + ((i < 4) ? (ty * 4 + i) : (64 + ty * 4 + i - 4));
        float bval = bias[o];
        #pragma unroll
        for (int j = 0; j < 8; j++) {
            int n = nn + ((j < 4) ? (tx * 4 + j) : (64 + tx * 4 + j - 4));
            if (n >= N) continue;
            dst[((size_t)b * 256 + o) * CPIX + PB[l] + n] = fmaxf(acc[i][j] + bval, 0.f);
        }
    }
}

// ---------------------------------------------------------------------------
// Merged up / head convs over 5 levels (3x3 pad1) on concat buffers.
// EPI 1: relu -> g_u concat.  EPI 2: heads -> final out.
// grid.x = 36+9+2+1+1 = 49
// ---------------------------------------------------------------------------
template <int EPI>
__global__ __launch_bounds__(256)
void conv_uphead(const float* __restrict__ src, const float* __restrict__ w,
                 const float* __restrict__ bias, float* __restrict__ dst,
                 int Cout)
{
    int tl = blockIdx.x, l;
    if (tl < 36)      { l = 0; }
    else if (tl < 45) { l = 1; tl -= 36; }
    else if (tl < 47) { l = 2; tl -= 45; }
    else if (tl < 48) { l = 3; tl -= 47; }
    else              { l = 4; tl -= 48; }
    const int OWs[5] = {67, 33, 16, 8, 4};
    const int PB[5]  = {0, 4489, 5578, 5834, 5898};
    const int RO[5]  = {0, 13467, 16734, 17502, 17694};

    const int OW = OWs[l], N = OW * OW;
    const int b  = blockIdx.z;
    const int om = blockIdx.y * 128;
    const int nn = tl * 128;
    const int tid = threadIdx.x;

    __shared__ float As[2][8][128];
    __shared__ float Bs[2][8][128];
    float acc[8][8];
    #pragma unroll
    for (int i = 0; i < 8; i++)
        #pragma unroll
        for (int j = 0; j < 8; j++) acc[i][j] = 0.f;

    const float* inb = src + (size_t)b * 256 * CPIX + PB[l];
    const int n_idx = tid & 127;
    const int ng = nn + n_idx;
    const bool nok = ng < N;
    const int oy = nok ? ng / OW : 0;
    const int ox = nok ? ng % OW : 0;

    // concat input: channel stride is CPIX, spatial dims OW x OW, pad 1
    {
        // inline specialized mainloop (channel stride CPIX != IH*IW)
        const int kb = tid >> 7;
        const int a_o = tid >> 1;
        const int a_kq = (tid & 1) * 4;
        const int ao_g = om + a_o;
        const bool aok = ao_g < Cout;
        const int tx = tid & 15, ty = tid >> 4;
        float4 va; float vb[4];
        auto load_tile = [&](int k0) {
            va = make_float4(0.f, 0.f, 0.f, 0.f);
            if (aok)
                va = *reinterpret_cast<const float4*>(w + (size_t)ao_g * 2304 + (k0 + a_kq));
            #pragma unroll
            for (int pass = 0; pass < 4; pass++) {
                int kg = k0 + kb + pass * 2;
                float v = 0.f;
                if (nok) {
                    int ci = kg / 9;
                    int r = kg - ci * 9;
                    int ky = r / 3, kx = r - ky * 3;
                    int iy = oy + ky - 1, ix = ox + kx - 1;
                    if (iy >= 0 && iy < OW && ix >= 0 && ix < OW)
                        v = inb[(size_t)ci * CPIX + iy * OW + ix];
                }
                vb[pass] = v;
            }
        };
        auto store_tile = [&](int buf) {
            As[buf][a_kq + 0][a_o] = va.x;
            As[buf][a_kq + 1][a_o] = va.y;
            As[buf][a_kq + 2][a_o] = va.z;
            As[buf][a_kq + 3][a_o] = va.w;
            #pragma unroll
            for (int pass = 0; pass < 4; pass++)
                Bs[buf][kb + pass * 2][n_idx] = vb[pass];
        };
        auto compute = [&](int buf) {
            #pragma unroll
            for (int kk = 0; kk < 8; kk++) {
                float4 a0 = *reinterpret_cast<const float4*>(&As[buf][kk][ty * 4]);
                float4 a1 = *reinterpret_cast<const float4*>(&As[buf][kk][64 + ty * 4]);
                float4 b0 = *reinterpret_cast<const float4*>(&Bs[buf][kk][tx * 4]);
                float4 b1 = *reinterpret_cast<const float4*>(&Bs[buf][kk][64 + tx * 4]);
                float av[8] = {a0.x, a0.y, a0.z, a0.w, a1.x, a1.y, a1.z, a1.w};
                float bv[8] = {b0.x, b0.y, b0.z, b0.w, b1.x, b1.y, b1.z, b1.w};
                #pragma unroll
                for (int i = 0; i < 8; i++)
                    #pragma unroll
                    for (int j = 0; j < 8; j++)
                        acc[i][j] = fmaf(av[i], bv[j], acc[i][j]);
            }
        };
        load_tile(0);
        store_tile(0);
        __syncthreads();
        int cur = 0;
        for (int k0 = 8; k0 < 2304; k0 += 8) {
            load_tile(k0);
            compute(cur);
            store_tile(1 - cur);
            __syncthreads();
            cur ^= 1;
        }
        compute(cur);
    }

    const int tx = tid & 15, ty = tid >> 4;
    #pragma unroll
    for (int i = 0; i < 8; i++) {
        int o = om + ((i < 4) ? (ty * 4 + i) : (64 + ty * 4 + i - 4));
        if (o >= Cout) continue;
        float bval = bias[o];
        #pragma unroll
        for (int j = 0; j < 8; j++) {
            int n = nn + ((j < 4) ? (tx * 4 + j) : (64 + tx * 4 + j - 4));
            if (n >= N) continue;
            float v = acc[i][j] + bval;
            if (EPI == 1) {
                dst[((size_t)b * 256 + o) * CPIX + PB[l] + n] = fmaxf(v, 0.f);
            } else {
                int p, c;
                if (o < 12)       { p = o >> 2;       c = o & 3; }
                else if (o < 255) { int q = o - 12;   p = q / 81; c = 4 + (q - p * 81); }
                else              { int q = o - 255;  p = q >> 5; c = 85 + (q & 31); v = tanhf(v); }
                size_t row = (size_t)RO[l] + (size_t)n * 3 + p;
                dst[((size_t)b * TOTAL_ROWS + row) * 117 + c] = v;
            }
        }
    }
}

// bilinear resize (half-pixel centers, edge clamp) + accumulate into dst
__global__ void resize_add(const float* __restrict__ src, float* __restrict__ dst,
                           int IH, int IW, int OH, int OW)
{
    int idx = blockIdx.x * blockDim.x + threadIdx.x;
    int total = BATCH * 256 * OH * OW;
    if (idx >= total) return;
    int ox = idx % OW;
    int t  = idx / OW;
    int oyv = t % OH;
    int bc = t / OH;
    float sy = (oyv + 0.5f) * (float)IH / (float)OH - 0.5f;
    float sx = (ox  + 0.5f) * (float)IW / (float)OW - 0.5f;
    int y0 = (int)floorf(sy); float fy = sy - y0;
    int x0 = (int)floorf(sx); float fx = sx - x0;
    int y0c = min(max(y0, 0), IH - 1), y1c = min(max(y0 + 1, 0), IH - 1);
    int x0c = min(max(x0, 0), IW - 1), x1c = min(max(x0 + 1, 0), IW - 1);
    const float* s = src + (size_t)bc * IH * IW;
    float v = (1.f - fy) * ((1.f - fx) * s[y0c * IW + x0c] + fx * s[y0c * IW + x1c])
            +         fy * ((1.f - fx) * s[y1c * IW + x0c] + fx * s[y1c * IW + x1c]);
    dst[idx] += v;
}

// downsample within concat buffer: srcBase(16x16 etc) -> dstBase, stride CPIX
__global__ void downsample_c(float* __restrict__ p, int srcBase, int srcW,
                             int dstBase, int dstW)
{
    int idx = blockIdx.x * blockDim.x + threadIdx.x;
    int total = BATCH * 256 * dstW * dstW;
    if (idx >= total) return;
    int ox = idx % dstW;
    int t  = idx / dstW;
    int oyv = t % dstW;
    int bc = t / dstW;
    p[(size_t)bc * CPIX + dstBase + oyv * dstW + ox] =
        p[(size_t)bc * CPIX + srcBase + 2 * oyv * srcW + 2 * ox];
}

__global__ void concat_heads(const float* __restrict__ bw, const float* __restrict__ bb,
                             const float* __restrict__ cw, const float* __restrict__ cb,
                             const float* __restrict__ mw, const float* __restrict__ mb)
{
    int idx = blockIdx.x * blockDim.x + threadIdx.x;
    if (idx < 351 * 2304) {
        int o = idx / 2304, k = idx - o * 2304;
        float v;
        if (o < 12)       v = bw[idx];
        else if (o < 255) v = cw[(o - 12) * 2304 + k];
        else              v = mw[(o - 255) * 2304 + k];
        g_wh[idx] = v;
    }
    if (idx < 351) {
        g_bh[idx] = (idx < 12) ? bb[idx] : (idx < 255) ? cb[idx - 12] : mb[idx - 255];
    }
}

__global__ void priors_kernel(float* __restrict__ out)
{
    int idx = blockIdx.x * blockDim.x + threadIdx.x;
    if (idx >= TOTAL_ROWS) return;
    int ch, cw;
    if (idx < 13467)      { ch = 67; cw = 67; idx -= 0;     }
    else if (idx < 16734) { ch = 33; cw = 33; idx -= 13467; }
    else if (idx < 17502) { ch = 16; cw = 16; idx -= 16734; }
    else if (idx < 17694) { ch = 8;  cw = 8;  idx -= 17502; }
    else                  { ch = 4;  cw = 4;  idx -= 17694; }
    int gi = blockIdx.x * blockDim.x + threadIdx.x;
    int p = idx % 3;
    int n = idx / 3;
    int y = n / cw, x = n - y * cw;
    const float ar[3] = {1.0f, 0.5f, 2.0f};
    out[gi * 4 + 0] = (x + 0.5f) / cw;
    out[gi * 4 + 1] = (y + 0.5f) / ch;
    out[gi * 4 + 2] = 3.0f * ar[p] / cw;
    out[gi * 4 + 3] = 3.0f / ar[p] / ch;
}

static inline int cdiv(int a, int b) { return (a + b - 1) / b; }

extern "C" void kernel_launch(void* const* d_in, const int* in_sizes, int n_in,
                              void* d_out, int out_size)
{
    const float* c3      = (const float*)d_in[0];
    const float* c4      = (const float*)d_in[1];
    const float* c5      = (const float*)d_in[2];
    const float* lat_w5  = (const float*)d_in[3];
    const float* lat_b5  = (const float*)d_in[4];
    const float* lat_w4  = (const float*)d_in[5];
    const float* lat_b4  = (const float*)d_in[6];
    const float* lat_w3  = (const float*)d_in[7];
    const float* lat_b3  = (const float*)d_in[8];
    const float* pred_w0 = (const float*)d_in[9];
    const float* pred_b0 = (const float*)d_in[10];
    const float* pred_w1 = (const float*)d_in[11];
    const float* pred_b1 = (const float*)d_in[12];
    const float* pred_w2 = (const float*)d_in[13];
    const float* pred_b2 = (const float*)d_in[14];
    const float* up_w    = (const float*)d_in[15];
    const float* up_b    = (const float*)d_in[16];
    const float* bbox_w  = (const float*)d_in[17];
    const float* bbox_b  = (const float*)d_in[18];
    const float* conf_w  = (const float*)d_in[19];
    const float* conf_b  = (const float*)d_in[20];
    const float* mask_w  = (const float*)d_in[21];
    const float* mask_b  = (const float*)d_in[22];

    float* out = (float*)d_out;

    float *x5, *x4, *x3, *p, *u, *wh, *bh;
    cudaGetSymbolAddress((void**)&x5, g_x5);
    cudaGetSymbolAddress((void**)&x4, g_x4);
    cudaGetSymbolAddress((void**)&x3, g_x3);
    cudaGetSymbolAddress((void**)&p,  g_p);
    cudaGetSymbolAddress((void**)&u,  g_u);
    cudaGetSymbolAddress((void**)&wh, g_wh);
    cudaGetSymbolAddress((void**)&bh, g_bh);

    concat_heads<<<cdiv(351 * 2304, 256), 256>>>(bbox_w, bbox_b, conf_w, conf_b, mask_w, mask_b);
    priors_kernel<<<cdiv(TOTAL_ROWS, 256), 256>>>(out + OUT_ELEMS);

    // FPN lateral chain (1x1 convs + bilinear adds)
    conv_lat<<<dim3(cdiv(18 * 18, 128), 2, 8), 256>>>(c5, lat_w5, lat_b5, x5, 2048, 18 * 18);
    conv_lat<<<dim3(cdiv(35 * 35, 128), 2, 8), 256>>>(c4, lat_w4, lat_b4, x4, 1024, 35 * 35);
    resize_add<<<cdiv(BATCH * 256 * 35 * 35, 256), 256>>>(x5, x4, 18, 18, 35, 35);
    conv_lat<<<dim3(cdiv(69 * 69, 128), 2, 8), 256>>>(c3, lat_w3, lat_b3, x3, 512, 69 * 69);
    resize_add<<<cdiv(BATCH * 256 * 69 * 69, 256), 256>>>(x4, x3, 35, 35, 69, 69);

    // pred convs for p3/p4/p5 in ONE launch -> g_p concat levels 0..2
    conv_pred_merged<<<dim3(47, 2, 8), 256>>>(x3, x4, x5,
                                              pred_w0, pred_w1, pred_w2,
                                              pred_b0, pred_b1, pred_b2, p);
    // p6 = p5[::2,::2], p7 = p6[::2,::2] within concat buffer
    downsample_c<<<cdiv(BATCH * 256 * 64, 256), 256>>>(p, 5578, 16, 5834, 8);
    downsample_c<<<cdiv(BATCH * 256 * 16, 256), 256>>>(p, 5834, 8, 5898, 4);

    // shared head: ONE up launch + ONE head launch over all 5 levels
    conv_uphead<1><<<dim3(49, 2, 8), 256>>>(p, up_w, up_b, u, 256);
    conv_uphead<2><<<dim3(49, 3, 8), 256>>>(u, wh, bh, out, 351);
}

// round 9
// speedup vs baseline: 1.3046x; 1.0498x over previous
#include <cuda_runtime.h>
#include <math.h>

// ---------------------------------------------------------------------------
// Yolact head: FPN + shared prediction head, fp32, level-merged launches.
// Output: [0, 8*17742*117) out (B,rows,117); then prior (17742,4).
// Levels (concat pixel space, per batch): p3 4489 | p4 1089 | p5 256 | p6 64 | p7 16
// pixBase {0,4489,5578,5834,5898}, total 5914. rowOff = pixBase*3.
// ---------------------------------------------------------------------------

#define BATCH 8
#define TOTAL_ROWS 17742
#define OUT_ELEMS (8u * 17742u * 117u)
#define CPIX 5914            // concat pixels per (b, channel)

__device__ float g_x5[8 * 256 * 18 * 18];
__device__ float g_x4[8 * 256 * 35 * 35];
__device__ float g_x3[8 * 256 * 69 * 69];
__device__ float g_p [8 * 256 * CPIX];   // p3..p7 concat
__device__ float g_u [8 * 256 * CPIX];   // up-conv output concat
__device__ float g_wh[351 * 2304];
__device__ float g_bh[351];

// ---------------------------------------------------------------------------
// Shared double-buffered GEMM mainloop: 128x128 tile, BK=8, 8x8 split micro-tile.
// ---------------------------------------------------------------------------
template <int KW, int PAD>
__device__ __forceinline__ void gemm_loop(
    const float* __restrict__ w, int K, int Cout, int om,
    const float* __restrict__ inb, int IH, int IW, int OW, int chStride,
    bool nok, int oy, int ox, int tid,
    float (&acc)[8][8], float (&As)[2][8][128], float (&Bs)[2][8][128])
{
    const int n_idx = tid & 127;
    const int kb = tid >> 7;
    const int a_o = tid >> 1;
    const int a_kq = (tid & 1) * 4;
    const int ao_g = om + a_o;
    const bool aok = ao_g < Cout;
    const int tx = tid & 15, ty = tid >> 4;

    float4 va; float vb[4];

    auto load_tile = [&](int k0) {
        va = make_float4(0.f, 0.f, 0.f, 0.f);
        if (aok)
            va = *reinterpret_cast<const float4*>(w + (size_t)ao_g * K + (k0 + a_kq));
        #pragma unroll
        for (int pass = 0; pass < 4; pass++) {
            int kg = k0 + kb + pass * 2;
            float v = 0.f;
            if (nok) {
                int ci, iy, ix;
                if (KW == 1) { ci = kg; iy = oy; ix = ox; }
                else {
                    ci = kg / 9;
                    int r = kg - ci * 9;
                    int ky = r / 3, kx = r - ky * 3;
                    iy = oy + ky - PAD;
                    ix = ox + kx - PAD;
                }
                if (iy >= 0 && iy < IH && ix >= 0 && ix < IW)
                    v = inb[(size_t)ci * chStride + iy * IW + ix];
            }
            vb[pass] = v;
        }
    };
    auto store_tile = [&](int buf) {
        As[buf][a_kq + 0][a_o] = va.x;
        As[buf][a_kq + 1][a_o] = va.y;
        As[buf][a_kq + 2][a_o] = va.z;
        As[buf][a_kq + 3][a_o] = va.w;
        #pragma unroll
        for (int pass = 0; pass < 4; pass++)
            Bs[buf][kb + pass * 2][n_idx] = vb[pass];
    };
    auto compute = [&](int buf) {
        #pragma unroll
        for (int kk = 0; kk < 8; kk++) {
            float4 a0 = *reinterpret_cast<const float4*>(&As[buf][kk][ty * 4]);
            float4 a1 = *reinterpret_cast<const float4*>(&As[buf][kk][64 + ty * 4]);
            float4 b0 = *reinterpret_cast<const float4*>(&Bs[buf][kk][tx * 4]);
            float4 b1 = *reinterpret_cast<const float4*>(&Bs[buf][kk][64 + tx * 4]);
            float av[8] = {a0.x, a0.y, a0.z, a0.w, a1.x, a1.y, a1.z, a1.w};
            float bv[8] = {b0.x, b0.y, b0.z, b0.w, b1.x, b1.y, b1.z, b1.w};
            #pragma unroll
            for (int i = 0; i < 8; i++)
                #pragma unroll
                for (int j = 0; j < 8; j++)
                    acc[i][j] = fmaf(av[i], bv[j], acc[i][j]);
        }
    };

    load_tile(0);
    store_tile(0);
    __syncthreads();
    int cur = 0;
    for (int k0 = 8; k0 < K; k0 += 8) {
        load_tile(k0);
        compute(cur);
        store_tile(1 - cur);
        __syncthreads();
        cur ^= 1;
    }
    compute(cur);
}

// ---------------------------------------------------------------------------
// Merged lateral 1x1 convs (3 levels, one launch).
// level0: c3 (Cin 512, 69x69, 38 tiles), level1: c4 (1024, 35x35, 10),
// level2: c5 (2048, 18x18, 3). grid.x = 51.
// ---------------------------------------------------------------------------
__global__ __launch_bounds__(256, 2)
void conv_lat_merged(const float* __restrict__ c3, const float* __restrict__ c4,
                     const float* __restrict__ c5,
                     const float* __restrict__ w3, const float* __restrict__ w4,
                     const float* __restrict__ w5,
                     const float* __restrict__ b3, const float* __restrict__ b4,
                     const float* __restrict__ b5,
                     float* __restrict__ x3, float* __restrict__ x4,
                     float* __restrict__ x5)
{
    int tl = blockIdx.x, l;
    if (tl < 38)      { l = 0; }
    else if (tl < 48) { l = 1; tl -= 38; }
    else              { l = 2; tl -= 48; }
    const int Cins[3] = {512, 1024, 2048};
    const int HWs[3]  = {4761, 1225, 324};
    const float* ins[3] = {c3, c4, c5};
    const float* ws[3]  = {w3, w4, w5};
    const float* bs[3]  = {b3, b4, b5};
    float* outs[3] = {x3, x4, x5};

    const int Cin = Cins[l], HW = HWs[l];
    const int b  = blockIdx.z;
    const int om = blockIdx.y * 128;
    const int nn = tl * 128;
    const int tid = threadIdx.x;

    __shared__ float As[2][8][128];
    __shared__ float Bs[2][8][128];
    float acc[8][8];
    #pragma unroll
    for (int i = 0; i < 8; i++)
        #pragma unroll
        for (int j = 0; j < 8; j++) acc[i][j] = 0.f;

    const float* inb = ins[l] + (size_t)b * Cin * HW;
    const int n_idx = tid & 127;
    const int ng = nn + n_idx;
    const bool nok = ng < HW;
    gemm_loop<1, 0>(ws[l], Cin, 256, om, inb, 1, HW, HW, HW, nok, 0, nok ? ng : 0,
                    tid, acc, As, Bs);

    const float* bias = bs[l];
    float* outp = outs[l];
    const int tx = tid & 15, ty = tid >> 4;
    #pragma unroll
    for (int i = 0; i < 8; i++) {
        int o = om + ((i < 4) ? (ty * 4 + i) : (64 + ty * 4 + i - 4));
        float bval = bias[o];
        #pragma unroll
        for (int j = 0; j < 8; j++) {
            int n = nn + ((j < 4) ? (tx * 4 + j) : (64 + tx * 4 + j - 4));
            if (n >= HW) continue;
            outp[((size_t)b * 256 + o) * HW + n] = acc[i][j] + bval;
        }
    }
}

// ---------------------------------------------------------------------------
// Merged pred convs (3 levels): 3x3 pad0, relu, write into g_p concat.
// grid.x = 36+9+2 = 47
// ---------------------------------------------------------------------------
__global__ __launch_bounds__(256, 2)
void conv_pred_merged(const float* __restrict__ x3, const float* __restrict__ x4,
                      const float* __restrict__ x5,
                      const float* __restrict__ w0, const float* __restrict__ w1,
                      const float* __restrict__ w2,
                      const float* __restrict__ b0, const float* __restrict__ b1,
                      const float* __restrict__ b2,
                      float* __restrict__ dst)
{
    int tl = blockIdx.x, l;
    if (tl < 36)      { l = 0; }
    else if (tl < 45) { l = 1; tl -= 36; }
    else              { l = 2; tl -= 45; }
    const int OWs[3] = {67, 33, 16};
    const int IHs[3] = {69, 35, 18};
    const int PB[3]  = {0, 4489, 5578};
    const float* ins[3] = {x3, x4, x5};
    const float* ws[3]  = {w2, w1, w0};
    const float* bs[3]  = {b2, b1, b0};

    const int OW = OWs[l], IH = IHs[l], N = OW * OW;
    const int b  = blockIdx.z;
    const int om = blockIdx.y * 128;
    const int nn = tl * 128;
    const int tid = threadIdx.x;

    __shared__ float As[2][8][128];
    __shared__ float Bs[2][8][128];
    float acc[8][8];
    #pragma unroll
    for (int i = 0; i < 8; i++)
        #pragma unroll
        for (int j = 0; j < 8; j++) acc[i][j] = 0.f;

    const float* inb = ins[l] + (size_t)b * 256 * IH * IH;
    const int n_idx = tid & 127;
    const int ng = nn + n_idx;
    const bool nok = ng < N;
    const int oy = nok ? ng / OW : 0;
    const int ox = nok ? ng % OW : 0;

    gemm_loop<3, 0>(ws[l], 2304, 256, om, inb, IH, IH, OW, IH * IH, nok, oy, ox,
                    tid, acc, As, Bs);

    const float* bias = bs[l];
    const int tx = tid & 15, ty = tid >> 4;
    #pragma unroll
    for (int i = 0; i < 8; i++) {
        int o = om + ((i < 4) ? (ty * 4 + i) : (64 + ty * 4 + i - 4));
        float bval = bias[o];
        #pragma unroll
        for (int j = 0; j < 8; j++) {
            int n = nn + ((j < 4) ? (tx * 4 + j) : (64 + tx * 4 + j - 4));
            if (n >= N) continue;
            dst[((size_t)b * 256 + o) * CPIX + PB[l] + n] = fmaxf(acc[i][j] + bval, 0.f);
        }
    }
}

// ---------------------------------------------------------------------------
// Merged up / head convs over 5 levels (3x3 pad1) on concat buffers.
// EPI 1: relu -> g_u concat.  EPI 2: heads -> final out. grid.x = 49.
// ---------------------------------------------------------------------------
template <int EPI>
__global__ __launch_bounds__(256, 2)
void conv_uphead(const float* __restrict__ src, const float* __restrict__ w,
                 const float* __restrict__ bias, float* __restrict__ dst,
                 int Cout)
{
    int tl = blockIdx.x, l;
    if (tl < 36)      { l = 0; }
    else if (tl < 45) { l = 1; tl -= 36; }
    else if (tl < 47) { l = 2; tl -= 45; }
    else if (tl < 48) { l = 3; tl -= 47; }
    else              { l = 4; tl -= 48; }
    const int OWs[5] = {67, 33, 16, 8, 4};
    const int PB[5]  = {0, 4489, 5578, 5834, 5898};
    const int RO[5]  = {0, 13467, 16734, 17502, 17694};

    const int OW = OWs[l], N = OW * OW;
    const int b  = blockIdx.z;
    const int om = blockIdx.y * 128;
    const int nn = tl * 128;
    const int tid = threadIdx.x;

    __shared__ float As[2][8][128];
    __shared__ float Bs[2][8][128];
    float acc[8][8];
    #pragma unroll
    for (int i = 0; i < 8; i++)
        #pragma unroll
        for (int j = 0; j < 8; j++) acc[i][j] = 0.f;

    const float* inb = src + (size_t)b * 256 * CPIX + PB[l];
    const int n_idx = tid & 127;
    const int ng = nn + n_idx;
    const bool nok = ng < N;
    const int oy = nok ? ng / OW : 0;
    const int ox = nok ? ng % OW : 0;

    gemm_loop<3, 1>(w, 2304, Cout, om, inb, OW, OW, OW, CPIX, nok, oy, ox,
                    tid, acc, As, Bs);

    const int tx = tid & 15, ty = tid >> 4;
    #pragma unroll
    for (int i = 0; i < 8; i++) {
        int o = om + ((i < 4) ? (ty * 4 + i) : (64 + ty * 4 + i - 4));
        if (o >= Cout) continue;
        float bval = bias[o];
        #pragma unroll
        for (int j = 0; j < 8; j++) {
            int n = nn + ((j < 4) ? (tx * 4 + j) : (64 + tx * 4 + j - 4));
            if (n >= N) continue;
            float v = acc[i][j] + bval;
            if (EPI == 1) {
                dst[((size_t)b * 256 + o) * CPIX + PB[l] + n] = fmaxf(v, 0.f);
            } else {
                int p, c;
                if (o < 12)       { p = o >> 2;       c = o & 3; }
                else if (o < 255) { int q = o - 12;   p = q / 81; c = 4 + (q - p * 81); }
                else              { int q = o - 255;  p = q >> 5; c = 85 + (q & 31); v = tanhf(v); }
                size_t row = (size_t)RO[l] + (size_t)n * 3 + p;
                dst[((size_t)b * TOTAL_ROWS + row) * 117 + c] = v;
            }
        }
    }
}

// bilinear resize (half-pixel centers, edge clamp) + accumulate into dst
__global__ void resize_add(const float* __restrict__ src, float* __restrict__ dst,
                           int IH, int IW, int OH, int OW)
{
    int idx = blockIdx.x * blockDim.x + threadIdx.x;
    int total = BATCH * 256 * OH * OW;
    if (idx >= total) return;
    int ox = idx % OW;
    int t  = idx / OW;
    int oyv = t % OH;
    int bc = t / OH;
    float sy = (oyv + 0.5f) * (float)IH / (float)OH - 0.5f;
    float sx = (ox  + 0.5f) * (float)IW / (float)OW - 0.5f;
    int y0 = (int)floorf(sy); float fy = sy - y0;
    int x0 = (int)floorf(sx); float fx = sx - x0;
    int y0c = min(max(y0, 0), IH - 1), y1c = min(max(y0 + 1, 0), IH - 1);
    int x0c = min(max(x0, 0), IW - 1), x1c = min(max(x0 + 1, 0), IW - 1);
    const float* s = src + (size_t)bc * IH * IW;
    float v = (1.f - fy) * ((1.f - fx) * s[y0c * IW + x0c] + fx * s[y0c * IW + x1c])
            +         fy * ((1.f - fx) * s[y1c * IW + x0c] + fx * s[y1c * IW + x1c]);
    dst[idx] += v;
}

// downsample within concat buffer
__global__ void downsample_c(float* __restrict__ p, int srcBase, int srcW,
                             int dstBase, int dstW)
{
    int idx = blockIdx.x * blockDim.x + threadIdx.x;
    int total = BATCH * 256 * dstW * dstW;
    if (idx >= total) return;
    int ox = idx % dstW;
    int t  = idx / dstW;
    int oyv = t % dstW;
    int bc = t / dstW;
    p[(size_t)bc * CPIX + dstBase + oyv * dstW + ox] =
        p[(size_t)bc * CPIX + srcBase + 2 * oyv * srcW + 2 * ox];
}

__global__ void concat_heads(const float* __restrict__ bw, const float* __restrict__ bb,
                             const float* __restrict__ cw, const float* __restrict__ cb,
                             const float* __restrict__ mw, const float* __restrict__ mb)
{
    int idx = blockIdx.x * blockDim.x + threadIdx.x;
    if (idx < 351 * 2304) {
        int o = idx / 2304, k = idx - o * 2304;
        float v;
        if (o < 12)       v = bw[idx];
        else if (o < 255) v = cw[(o - 12) * 2304 + k];
        else              v = mw[(o - 255) * 2304 + k];
        g_wh[idx] = v;
    }
    if (idx < 351) {
        g_bh[idx] = (idx < 12) ? bb[idx] : (idx < 255) ? cb[idx - 12] : mb[idx - 255];
    }
}

__global__ void priors_kernel(float* __restrict__ out)
{
    int idx = blockIdx.x * blockDim.x + threadIdx.x;
    if (idx >= TOTAL_ROWS) return;
    int gi = idx;
    int ch, cw;
    if (idx < 13467)      { ch = 67; cw = 67; idx -= 0;     }
    else if (idx < 16734) { ch = 33; cw = 33; idx -= 13467; }
    else if (idx < 17502) { ch = 16; cw = 16; idx -= 16734; }
    else if (idx < 17694) { ch = 8;  cw = 8;  idx -= 17502; }
    else                  { ch = 4;  cw = 4;  idx -= 17694; }
    int p = idx % 3;
    int n = idx / 3;
    int y = n / cw, x = n - y * cw;
    const float ar[3] = {1.0f, 0.5f, 2.0f};
    out[gi * 4 + 0] = (x + 0.5f) / cw;
    out[gi * 4 + 1] = (y + 0.5f) / ch;
    out[gi * 4 + 2] = 3.0f * ar[p] / cw;
    out[gi * 4 + 3] = 3.0f / ar[p] / ch;
}

static inline int cdiv(int a, int b) { return (a + b - 1) / b; }

extern "C" void kernel_launch(void* const* d_in, const int* in_sizes, int n_in,
                              void* d_out, int out_size)
{
    const float* c3      = (const float*)d_in[0];
    const float* c4      = (const float*)d_in[1];
    const float* c5      = (const float*)d_in[2];
    const float* lat_w5  = (const float*)d_in[3];
    const float* lat_b5  = (const float*)d_in[4];
    const float* lat_w4  = (const float*)d_in[5];
    const float* lat_b4  = (const float*)d_in[6];
    const float* lat_w3  = (const float*)d_in[7];
    const float* lat_b3  = (const float*)d_in[8];
    const float* pred_w0 = (const float*)d_in[9];
    const float* pred_b0 = (const float*)d_in[10];
    const float* pred_w1 = (const float*)d_in[11];
    const float* pred_b1 = (const float*)d_in[12];
    const float* pred_w2 = (const float*)d_in[13];
    const float* pred_b2 = (const float*)d_in[14];
    const float* up_w    = (const float*)d_in[15];
    const float* up_b    = (const float*)d_in[16];
    const float* bbox_w  = (const float*)d_in[17];
    const float* bbox_b  = (const float*)d_in[18];
    const float* conf_w  = (const float*)d_in[19];
    const float* conf_b  = (const float*)d_in[20];
    const float* mask_w  = (const float*)d_in[21];
    const float* mask_b  = (const float*)d_in[22];

    float* out = (float*)d_out;

    float *x5, *x4, *x3, *p, *u, *wh, *bh;
    cudaGetSymbolAddress((void**)&x5, g_x5);
    cudaGetSymbolAddress((void**)&x4, g_x4);
    cudaGetSymbolAddress((void**)&x3, g_x3);
    cudaGetSymbolAddress((void**)&p,  g_p);
    cudaGetSymbolAddress((void**)&u,  g_u);
    cudaGetSymbolAddress((void**)&wh, g_wh);
    cudaGetSymbolAddress((void**)&bh, g_bh);

    concat_heads<<<cdiv(351 * 2304, 256), 256>>>(bbox_w, bbox_b, conf_w, conf_b, mask_w, mask_b);
    priors_kernel<<<cdiv(TOTAL_ROWS, 256), 256>>>(out + OUT_ELEMS);

    // all three FPN lateral 1x1 convs in ONE launch
    conv_lat_merged<<<dim3(51, 2, 8), 256>>>(c3, c4, c5,
                                             lat_w3, lat_w4, lat_w5,
                                             lat_b3, lat_b4, lat_b5,
                                             x3, x4, x5);
    resize_add<<<cdiv(BATCH * 256 * 35 * 35, 256), 256>>>(x5, x4, 18, 18, 35, 35);
    resize_add<<<cdiv(BATCH * 256 * 69 * 69, 256), 256>>>(x4, x3, 35, 35, 69, 69);

    // pred convs for p3/p4/p5 in ONE launch -> g_p concat levels 0..2
    conv_pred_merged<<<dim3(47, 2, 8), 256>>>(x3, x4, x5,
                                              pred_w0, pred_w1, pred_w2,
                                              pred_b0, pred_b1, pred_b2, p);
    downsample_c<<<cdiv(BATCH * 256 * 64, 256), 256>>>(p, 5578, 16, 5834, 8);
    downsample_c<<<cdiv(BATCH * 256 * 16, 256), 256>>>(p, 5834, 8, 5898, 4);

    // shared head: ONE up launch + ONE head launch over all 5 levels
    conv_uphead<1><<<dim3(49, 2, 8), 256>>>(p, up_w, up_b, u, 256);
    conv_uphead<2><<<dim3(49, 3, 8), 256>>>(u, wh, bh, out, 351);
}

// round 13
// speedup vs baseline: 1.4720x; 1.1283x over previous
#include <cuda_runtime.h>
#include <math.h>

// ---------------------------------------------------------------------------
// Yolact head: FPN + shared prediction head, fp32, level-merged launches.
// GEMM inner loop uses packed fma.rn.f32x2 (FFMA2) -> 2x fp32 FLOP ceiling.
// Output: [0, 8*17742*117) out (B,rows,117); then prior (17742,4).
// Levels (concat pixel space, per batch): p3 4489 | p4 1089 | p5 256 | p6 64 | p7 16
// pixBase {0,4489,5578,5834,5898}, total 5914. rowOff = pixBase*3.
// ---------------------------------------------------------------------------

#define BATCH 8
#define TOTAL_ROWS 17742
#define OUT_ELEMS (8u * 17742u * 117u)
#define CPIX 5914            // concat pixels per (b, channel)

__device__ float g_x5[8 * 256 * 18 * 18];
__device__ float g_x4[8 * 256 * 35 * 35];
__device__ float g_x3[8 * 256 * 69 * 69];
__device__ float g_p [8 * 256 * CPIX];   // p3..p7 concat
__device__ float g_u [8 * 256 * CPIX];   // up-conv output concat
__device__ float g_wh[351 * 2304];
__device__ float g_bh[351];

// ---- packed f32x2 helpers (sm_103a FFMA2 path; PTX-only) -------------------
__device__ __forceinline__ unsigned long long pack2(float lo, float hi) {
    unsigned long long r;
    asm("mov.b64 %0, {%1, %2};" : "=l"(r) : "f"(lo), "f"(hi));
    return r;
}
__device__ __forceinline__ void fma2(unsigned long long& d,
                                     unsigned long long a, unsigned long long b) {
    asm("fma.rn.f32x2 %0, %1, %2, %3;" : "=l"(d) : "l"(a), "l"(b), "l"(d));
}
__device__ __forceinline__ void unpack2(unsigned long long v, float& lo, float& hi) {
    asm("mov.b64 {%0, %1}, %2;" : "=f"(lo), "=f"(hi) : "l"(v));
}

// ---------------------------------------------------------------------------
// Shared double-buffered GEMM mainloop: 128x128 tile, BK=8, 8x8 split micro-tile,
// accumulators as 8x4 packed f32x2 (pairs along the pixel axis).
// ---------------------------------------------------------------------------
template <int KW, int PAD>
__device__ __forceinline__ void gemm_loop(
    const float* __restrict__ w, int K, int Cout, int om,
    const float* __restrict__ inb, int IH, int IW, int OW, int chStride,
    bool nok, int oy, int ox, int tid,
    unsigned long long (&acc)[8][4],
    float (&As)[2][8][128], float (&Bs)[2][8][128])
{
    const int n_idx = tid & 127;
    const int kb = tid >> 7;
    const int a_o = tid >> 1;
    const int a_kq = (tid & 1) * 4;
    const int ao_g = om + a_o;
    const bool aok = ao_g < Cout;
    const int tx = tid & 15, ty = tid >> 4;

    float4 va; float vb[4];

    auto load_tile = [&](int k0) {
        va = make_float4(0.f, 0.f, 0.f, 0.f);
        if (aok)
            va = *reinterpret_cast<const float4*>(w + (size_t)ao_g * K + (k0 + a_kq));
        #pragma unroll
        for (int pass = 0; pass < 4; pass++) {
            int kg = k0 + kb + pass * 2;
            float v = 0.f;
            if (nok) {
                int ci, iy, ix;
                if (KW == 1) { ci = kg; iy = oy; ix = ox; }
                else {
                    ci = kg / 9;
                    int r = kg - ci * 9;
                    int ky = r / 3, kx = r - ky * 3;
                    iy = oy + ky - PAD;
                    ix = ox + kx - PAD;
                }
                if (iy >= 0 && iy < IH && ix >= 0 && ix < IW)
                    v = inb[(size_t)ci * chStride + iy * IW + ix];
            }
            vb[pass] = v;
        }
    };
    auto store_tile = [&](int buf) {
        As[buf][a_kq + 0][a_o] = va.x;
        As[buf][a_kq + 1][a_o] = va.y;
        As[buf][a_kq + 2][a_o] = va.z;
        As[buf][a_kq + 3][a_o] = va.w;
        #pragma unroll
        for (int pass = 0; pass < 4; pass++)
            Bs[buf][kb + pass * 2][n_idx] = vb[pass];
    };
    auto compute = [&](int buf) {
        #pragma unroll
        for (int kk = 0; kk < 8; kk++) {
            float4 a0 = *reinterpret_cast<const float4*>(&As[buf][kk][ty * 4]);
            float4 a1 = *reinterpret_cast<const float4*>(&As[buf][kk][64 + ty * 4]);
            float4 b0 = *reinterpret_cast<const float4*>(&Bs[buf][kk][tx * 4]);
            float4 b1 = *reinterpret_cast<const float4*>(&Bs[buf][kk][64 + tx * 4]);
            float av[8] = {a0.x, a0.y, a0.z, a0.w, a1.x, a1.y, a1.z, a1.w};
            unsigned long long bp[4];
            bp[0] = pack2(b0.x, b0.y);
            bp[1] = pack2(b0.z, b0.w);
            bp[2] = pack2(b1.x, b1.y);
            bp[3] = pack2(b1.z, b1.w);
            #pragma unroll
            for (int i = 0; i < 8; i++) {
                unsigned long long ap = pack2(av[i], av[i]);
                #pragma unroll
                for (int jj = 0; jj < 4; jj++)
                    fma2(acc[i][jj], ap, bp[jj]);
            }
        }
    };

    load_tile(0);
    store_tile(0);
    __syncthreads();
    int cur = 0;
    for (int k0 = 8; k0 < K; k0 += 8) {
        load_tile(k0);
        compute(cur);
        store_tile(1 - cur);
        __syncthreads();
        cur ^= 1;
    }
    compute(cur);
}

// ---------------------------------------------------------------------------
// Merged lateral 1x1 convs (3 levels, one launch). grid.x = 51.
// ---------------------------------------------------------------------------
__global__ __launch_bounds__(256, 2)
void conv_lat_merged(const float* __restrict__ c3, const float* __restrict__ c4,
                     const float* __restrict__ c5,
                     const float* __restrict__ w3, const float* __restrict__ w4,
                     const float* __restrict__ w5,
                     const float* __restrict__ b3, const float* __restrict__ b4,
                     const float* __restrict__ b5,
                     float* __restrict__ x3, float* __restrict__ x4,
                     float* __restrict__ x5)
{
    int tl = blockIdx.x, l;
    if (tl < 38)      { l = 0; }
    else if (tl < 48) { l = 1; tl -= 38; }
    else              { l = 2; tl -= 48; }
    const int Cins[3] = {512, 1024, 2048};
    const int HWs[3]  = {4761, 1225, 324};
    const float* ins[3] = {c3, c4, c5};
    const float* ws[3]  = {w3, w4, w5};
    const float* bs[3]  = {b3, b4, b5};
    float* outs[3] = {x3, x4, x5};

    const int Cin = Cins[l], HW = HWs[l];
    const int b  = blockIdx.z;
    const int om = blockIdx.y * 128;
    const int nn = tl * 128;
    const int tid = threadIdx.x;

    __shared__ float As[2][8][128];
    __shared__ float Bs[2][8][128];
    unsigned long long acc[8][4];
    #pragma unroll
    for (int i = 0; i < 8; i++)
        #pragma unroll
        for (int j = 0; j < 4; j++) acc[i][j] = 0ull;

    const float* inb = ins[l] + (size_t)b * Cin * HW;
    const int n_idx = tid & 127;
    const int ng = nn + n_idx;
    const bool nok = ng < HW;
    gemm_loop<1, 0>(ws[l], Cin, 256, om, inb, 1, HW, HW, HW, nok, 0, nok ? ng : 0,
                    tid, acc, As, Bs);

    const float* bias = bs[l];
    float* outp = outs[l];
    const int tx = tid & 15, ty = tid >> 4;
    #pragma unroll
    for (int i = 0; i < 8; i++) {
        int o = om + ((i < 4) ? (ty * 4 + i) : (64 + ty * 4 + i - 4));
        float bval = bias[o];
        #pragma unroll
        for (int jj = 0; jj < 4; jj++) {
            float v2[2];
            unpack2(acc[i][jj], v2[0], v2[1]);
            #pragma unroll
            for (int s = 0; s < 2; s++) {
                int j = jj * 2 + s;
                int n = nn + ((j < 4) ? (tx * 4 + j) : (64 + tx * 4 + j - 4));
                if (n >= HW) continue;
                outp[((size_t)b * 256 + o) * HW + n] = v2[s] + bval;
            }
        }
    }
}

// ---------------------------------------------------------------------------
// Merged pred convs (3 levels): 3x3 pad0, relu, write into g_p concat. grid.x=47
// ---------------------------------------------------------------------------
__global__ __launch_bounds__(256, 2)
void conv_pred_merged(const float* __restrict__ x3, const float* __restrict__ x4,
                      const float* __restrict__ x5,
                      const float* __restrict__ w0, const float* __restrict__ w1,
                      const float* __restrict__ w2,
                      const float* __restrict__ b0, const float* __restrict__ b1,
                      const float* __restrict__ b2,
                      float* __restrict__ dst)
{
    int tl = blockIdx.x, l;
    if (tl < 36)      { l = 0; }
    else if (tl < 45) { l = 1; tl -= 36; }
    else              { l = 2; tl -= 45; }
    const int OWs[3] = {67, 33, 16};
    const int IHs[3] = {69, 35, 18};
    const int PB[3]  = {0, 4489, 5578};
    const float* ins[3] = {x3, x4, x5};
    const float* ws[3]  = {w2, w1, w0};
    const float* bs[3]  = {b2, b1, b0};

    const int OW = OWs[l], IH = IHs[l], N = OW * OW;
    const int b  = blockIdx.z;
    const int om = blockIdx.y * 128;
    const int nn = tl * 128;
    const int tid = threadIdx.x;

    __shared__ float As[2][8][128];
    __shared__ float Bs[2][8][128];
    unsigned long long acc[8][4];
    #pragma unroll
    for (int i = 0; i < 8; i++)
        #pragma unroll
        for (int j = 0; j < 4; j++) acc[i][j] = 0ull;

    const float* inb = ins[l] + (size_t)b * 256 * IH * IH;
    const int n_idx = tid & 127;
    const int ng = nn + n_idx;
    const bool nok = ng < N;
    const int oy = nok ? ng / OW : 0;
    const int ox = nok ? ng % OW : 0;

    gemm_loop<3, 0>(ws[l], 2304, 256, om, inb, IH, IH, OW, IH * IH, nok, oy, ox,
                    tid, acc, As, Bs);

    const float* bias = bs[l];
    const int tx = tid & 15, ty = tid >> 4;
    #pragma unroll
    for (int i = 0; i < 8; i++) {
        int o = om + ((i < 4) ? (ty * 4 + i) : (64 + ty * 4 + i - 4));
        float bval = bias[o];
        #pragma unroll
        for (int jj = 0; jj < 4; jj++) {
            float v2[2];
            unpack2(acc[i][jj], v2[0], v2[1]);
            #pragma unroll
            for (int s = 0; s < 2; s++) {
                int j = jj * 2 + s;
                int n = nn + ((j < 4) ? (tx * 4 + j) : (64 + tx * 4 + j - 4));
                if (n >= N) continue;
                dst[((size_t)b * 256 + o) * CPIX + PB[l] + n] = fmaxf(v2[s] + bval, 0.f);
            }
        }
    }
}

// ---------------------------------------------------------------------------
// Merged up / head convs over 5 levels (3x3 pad1) on concat buffers.
// EPI 1: relu -> g_u concat.  EPI 2: heads -> final out. grid.x = 49.
// ---------------------------------------------------------------------------
template <int EPI>
__global__ __launch_bounds__(256, 2)
void conv_uphead(const float* __restrict__ src, const float* __restrict__ w,
                 const float* __restrict__ bias, float* __restrict__ dst,
                 int Cout)
{
    int tl = blockIdx.x, l;
    if (tl < 36)      { l = 0; }
    else if (tl < 45) { l = 1; tl -= 36; }
    else if (tl < 47) { l = 2; tl -= 45; }
    else if (tl < 48) { l = 3; tl -= 47; }
    else              { l = 4; tl -= 48; }
    const int OWs[5] = {67, 33, 16, 8, 4};
    const int PB[5]  = {0, 4489, 5578, 5834, 5898};
    const int RO[5]  = {0, 13467, 16734, 17502, 17694};

    const int OW = OWs[l], N = OW * OW;
    const int b  = blockIdx.z;
    const int om = blockIdx.y * 128;
    const int nn = tl * 128;
    const int tid = threadIdx.x;

    __shared__ float As[2][8][128];
    __shared__ float Bs[2][8][128];
    unsigned long long acc[8][4];
    #pragma unroll
    for (int i = 0; i < 8; i++)
        #pragma unroll
        for (int j = 0; j < 4; j++) acc[i][j] = 0ull;

    const float* inb = src + (size_t)b * 256 * CPIX + PB[l];
    const int n_idx = tid & 127;
    const int ng = nn + n_idx;
    const bool nok = ng < N;
    const int oy = nok ? ng / OW : 0;
    const int ox = nok ? ng % OW : 0;

    gemm_loop<3, 1>(w, 2304, Cout, om, inb, OW, OW, OW, CPIX, nok, oy, ox,
                    tid, acc, As, Bs);

    const int tx = tid & 15, ty = tid >> 4;
    #pragma unroll
    for (int i = 0; i < 8; i++) {
        int o = om + ((i < 4) ? (ty * 4 + i) : (64 + ty * 4 + i - 4));
        if (o >= Cout) continue;
        float bval = bias[o];
        #pragma unroll
        for (int jj = 0; jj < 4; jj++) {
            float v2[2];
            unpack2(acc[i][jj], v2[0], v2[1]);
            #pragma unroll
            for (int s = 0; s < 2; s++) {
                int j = jj * 2 + s;
                int n = nn + ((j < 4) ? (tx * 4 + j) : (64 + tx * 4 + j - 4));
                if (n >= N) continue;
                float v = v2[s] + bval;
                if (EPI == 1) {
                    dst[((size_t)b * 256 + o) * CPIX + PB[l] + n] = fmaxf(v, 0.f);
                } else {
                    int p, c;
                    if (o < 12)       { p = o >> 2;       c = o & 3; }
                    else if (o < 255) { int q = o - 12;   p = q / 81; c = 4 + (q - p * 81); }
                    else              { int q = o - 255;  p = q >> 5; c = 85 + (q & 31); v = tanhf(v); }
                    size_t row = (size_t)RO[l] + (size_t)n * 3 + p;
                    dst[((size_t)b * TOTAL_ROWS + row) * 117 + c] = v;
                }
            }
        }
    }
}

// bilinear resize (half-pixel centers, edge clamp) + accumulate into dst
__global__ void resize_add(const float* __restrict__ src, float* __restrict__ dst,
                           int IH, int IW, int OH, int OW)
{
    int idx = blockIdx.x * blockDim.x + threadIdx.x;
    int total = BATCH * 256 * OH * OW;
    if (idx >= total) return;
    int ox = idx % OW;
    int t  = idx / OW;
    int oyv = t % OH;
    int bc = t / OH;
    float sy = (oyv + 0.5f) * (float)IH / (float)OH - 0.5f;
    float sx = (ox  + 0.5f) * (float)IW / (float)OW - 0.5f;
    int y0 = (int)floorf(sy); float fy = sy - y0;
    int x0 = (int)floorf(sx); float fx = sx - x0;
    int y0c = min(max(y0, 0), IH - 1), y1c = min(max(y0 + 1, 0), IH - 1);
    int x0c = min(max(x0, 0), IW - 1), x1c = min(max(x0 + 1, 0), IW - 1);
    const float* s = src + (size_t)bc * IH * IW;
    float v = (1.f - fy) * ((1.f - fx) * s[y0c * IW + x0c] + fx * s[y0c * IW + x1c])
            +         fy * ((1.f - fx) * s[y1c * IW + x0c] + fx * s[y1c * IW + x1c]);
    dst[idx] += v;
}

// downsample within concat buffer
__global__ void downsample_c(float* __restrict__ p, int srcBase, int srcW,
                             int dstBase, int dstW)
{
    int idx = blockIdx.x * blockDim.x + threadIdx.x;
    int total = BATCH * 256 * dstW * dstW;
    if (idx >= total) return;
    int ox = idx % dstW;
    int t  = idx / dstW;
    int oyv = t % dstW;
    int bc = t / dstW;
    p[(size_t)bc * CPIX + dstBase + oyv * dstW + ox] =
        p[(size_t)bc * CPIX + srcBase + 2 * oyv * srcW + 2 * ox];
}

__global__ void concat_heads(const float* __restrict__ bw, const float* __restrict__ bb,
                             const float* __restrict__ cw, const float* __restrict__ cb,
                             const float* __restrict__ mw, const float* __restrict__ mb)
{
    int idx = blockIdx.x * blockDim.x + threadIdx.x;
    if (idx < 351 * 2304) {
        int o = idx / 2304, k = idx - o * 2304;
        float v;
        if (o < 12)       v = bw[idx];
        else if (o < 255) v = cw[(o - 12) * 2304 + k];
        else              v = mw[(o - 255) * 2304 + k];
        g_wh[idx] = v;
    }
    if (idx < 351) {
        g_bh[idx] = (idx < 12) ? bb[idx] : (idx < 255) ? cb[idx - 12] : mb[idx - 255];
    }
}

__global__ void priors_kernel(float* __restrict__ out)
{
    int idx = blockIdx.x * blockDim.x + threadIdx.x;
    if (idx >= TOTAL_ROWS) return;
    int gi = idx;
    int ch, cw;
    if (idx < 13467)      { ch = 67; cw = 67; idx -= 0;     }
    else if (idx < 16734) { ch = 33; cw = 33; idx -= 13467; }
    else if (idx < 17502) { ch = 16; cw = 16; idx -= 16734; }
    else if (idx < 17694) { ch = 8;  cw = 8;  idx -= 17502; }
    else                  { ch = 4;  cw = 4;  idx -= 17694; }
    int p = idx % 3;
    int n = idx / 3;
    int y = n / cw, x = n - y * cw;
    const float ar[3] = {1.0f, 0.5f, 2.0f};
    out[gi * 4 + 0] = (x + 0.5f) / cw;
    out[gi * 4 + 1] = (y + 0.5f) / ch;
    out[gi * 4 + 2] = 3.0f * ar[p] / cw;
    out[gi * 4 + 3] = 3.0f / ar[p] / ch;
}

static inline int cdiv(int a, int b) { return (a + b - 1) / b; }

extern "C" void kernel_launch(void* const* d_in, const int* in_sizes, int n_in,
                              void* d_out, int out_size)
{
    const float* c3      = (const float*)d_in[0];
    const float* c4      = (const float*)d_in[1];
    const float* c5      = (const float*)d_in[2];
    const float* lat_w5  = (const float*)d_in[3];
    const float* lat_b5  = (const float*)d_in[4];
    const float* lat_w4  = (const float*)d_in[5];
    const float* lat_b4  = (const float*)d_in[6];
    const float* lat_w3  = (const float*)d_in[7];
    const float* lat_b3  = (const float*)d_in[8];
    const float* pred_w0 = (const float*)d_in[9];
    const float* pred_b0 = (const float*)d_in[10];
    const float* pred_w1 = (const float*)d_in[11];
    const float* pred_b1 = (const float*)d_in[12];
    const float* pred_w2 = (const float*)d_in[13];
    const float* pred_b2 = (const float*)d_in[14];
    const float* up_w    = (const float*)d_in[15];
    const float* up_b    = (const float*)d_in[16];
    const float* bbox_w  = (const float*)d_in[17];
    const float* bbox_b  = (const float*)d_in[18];
    const float* conf_w  = (const float*)d_in[19];
    const float* conf_b  = (const float*)d_in[20];
    const float* mask_w  = (const float*)d_in[21];
    const float* mask_b  = (const float*)d_in[22];

    float* out = (float*)d_out;

    float *x5, *x4, *x3, *p, *u, *wh, *bh;
    cudaGetSymbolAddress((void**)&x5, g_x5);
    cudaGetSymbolAddress((void**)&x4, g_x4);
    cudaGetSymbolAddress((void**)&x3, g_x3);
    cudaGetSymbolAddress((void**)&p,  g_p);
    cudaGetSymbolAddress((void**)&u,  g_u);
    cudaGetSymbolAddress((void**)&wh, g_wh);
    cudaGetSymbolAddress((void**)&bh, g_bh);

    concat_heads<<<cdiv(351 * 2304, 256), 256>>>(bbox_w, bbox_b, conf_w, conf_b, mask_w, mask_b);
    priors_kernel<<<cdiv(TOTAL_ROWS, 256), 256>>>(out + OUT_ELEMS);

    // all three FPN lateral 1x1 convs in ONE launch
    conv_lat_merged<<<dim3(51, 2, 8), 256>>>(c3, c4, c5,
                                             lat_w3, lat_w4, lat_w5,
                                             lat_b3, lat_b4, lat_b5,
                                             x3, x4, x5);
    resize_add<<<cdiv(BATCH * 256 * 35 * 35, 256), 256>>>(x5, x4, 18, 18, 35, 35);
    resize_add<<<cdiv(BATCH * 256 * 69 * 69, 256), 256>>>(x4, x3, 35, 35, 69, 69);

    // pred convs for p3/p4/p5 in ONE launch -> g_p concat levels 0..2
    conv_pred_merged<<<dim3(47, 2, 8), 256>>>(x3, x4, x5,
                                              pred_w0, pred_w1, pred_w2,
                                              pred_b0, pred_b1, pred_b2, p);
    downsample_c<<<cdiv(BATCH * 256 * 64, 256), 256>>>(p, 5578, 16, 5834, 8);
    downsample_c<<<cdiv(BATCH * 256 * 16, 256), 256>>>(p, 5834, 8, 5898, 4);

    // shared head: ONE up launch + ONE head launch over all 5 levels
    conv_uphead<1><<<dim3(49, 2, 8), 256>>>(p, up_w, up_b, u, 256);
    conv_uphead<2><<<dim3(49, 3, 8), 256>>>(u, wh, bh, out, 351);
}